// round 14
// baseline (speedup 1.0000x reference)
#include <cuda_runtime.h>
#include <math.h>

#define NLAT  128
#define NLON  256
#define LMAX  50
#define MMAX  50
#define BATCH 2
#define NPTS  2048
#define MGRID (NLAT*NLON)
#define PI_F  3.14159265358979323846f

// finer bin grid: avg 1 point/cell
#define BINX 64
#define BINY 32
#define NBIN (BINX*BINY)          // 2048
#define HX (2.0f*PI_F/(float)BINX)
#define HY (PI_F/(float)BINY)
#define X0 (-PI_F)
#define Y0 (-PI_F)

#define NN_BLOCKS  128           // 64 x BATCH
#define SHT_BLOCKS (MMAX*BATCH)  // 100
#define ALL_BLOCKS (NN_BLOCKS + SHT_BLOCKS)

__device__ float g_ft[BATCH][NLON][NLAT];   // interpolated grid, TRANSPOSED
__device__ int   g_arrive[BATCH] = {0, 0};
__device__ int   g_done = 0;

__device__ __forceinline__ float f_rcp(float v)  { float r; asm("rcp.approx.f32 %0,%1;"  : "=f"(r) : "f"(v)); return r; }
__device__ __forceinline__ float f_div(float a, float b){ float r; asm("div.approx.f32 %0,%1,%2;" : "=f"(r) : "f"(a), "f"(b)); return r; }

struct SmemNN {
    float4 srt[NPTS];            // 32 KB
    int cnt[NBIN];               // 8 KB
    int start[NBIN];             // 8 KB
    int cur[NBIN];               // 8 KB
    int wsum[16];
};
struct SmemSHT {
    float ctab[NLON];
    float sW[NLAT * LMAX];       // 25.6 KB
    float sa[64];
    float sbb[64];
    float fre[NLAT];
    float pf[2][NLAT];
    float ps[4][64];
};

__device__ __forceinline__ int bin_of(float px, float py) {
    int bx = (int)floorf((px - X0) * (1.0f/HX));
    int by = (int)floorf((py - Y0) * (1.0f/HY));
    bx = min(max(bx, 0), BINX-1);
    by = min(max(by, 0), BINY-1);
    return by * BINX + bx;
}

// ---------------------------------------------------------------------------
// NN role (R10 structure; 2048 bins, 4 bins/thread in the scan)
// ---------------------------------------------------------------------------
__device__ void nn_role(const float* __restrict__ tgt, SmemNN* sm,
                        int nbid, int tid) {
    int b = nbid >> 6;
    int xb = nbid & 63;
    int lane = tid & 31, wrp = tid >> 5;

    float4 pv[4];
    #pragma unroll
    for (int u = 0; u < 4; u++) {
        int j = tid + u * 512;
        const float* tp = &tgt[(b * NPTS + j) * 3];
        float x = tp[0], y = tp[1], z = tp[2];
        float rho = sqrtf(x*x + y*y + z*z);
        float phi = atan2f(y, x);
        float th  = acosf(z / rho) - PI_F;
        float s2  = phi*phi + th*th;
        pv[u] = make_float4(phi, th, s2, rho);
    }

    #pragma unroll
    for (int u = 0; u < 4; u++) sm->cnt[tid * 4 + u] = 0;
    __syncthreads();
    #pragma unroll
    for (int u = 0; u < 4; u++)
        atomicAdd(&sm->cnt[bin_of(pv[u].x, pv[u].y)], 1);
    __syncthreads();

    // scan over 2048 bins: 4 consecutive bins per thread + warp-shfl scan
    int c0 = sm->cnt[tid * 4 + 0];
    int c1 = sm->cnt[tid * 4 + 1];
    int c2 = sm->cnt[tid * 4 + 2];
    int c3 = sm->cnt[tid * 4 + 3];
    int v = c0 + c1 + c2 + c3;
    int x = v;
    #pragma unroll
    for (int off = 1; off < 32; off <<= 1) {
        int y = __shfl_up_sync(0xFFFFFFFFu, x, off);
        if (lane >= off) x += y;
    }
    if (lane == 31) sm->wsum[wrp] = x;
    __syncthreads();
    if (wrp == 0) {
        int w = (lane < 16) ? sm->wsum[lane] : 0;
        #pragma unroll
        for (int off = 1; off < 16; off <<= 1) {
            int y = __shfl_up_sync(0xFFFFFFFFu, w, off);
            if (lane >= off) w += y;
        }
        if (lane < 16) sm->wsum[lane] = w;
    }
    __syncthreads();
    int base = x - v + (wrp > 0 ? sm->wsum[wrp - 1] : 0);
    sm->start[tid*4+0] = base;            sm->cur[tid*4+0] = base;
    sm->start[tid*4+1] = base + c0;       sm->cur[tid*4+1] = base + c0;
    sm->start[tid*4+2] = base + c0+c1;    sm->cur[tid*4+2] = base + c0+c1;
    sm->start[tid*4+3] = base + c0+c1+c2; sm->cur[tid*4+3] = base + c0+c1+c2;
    __syncthreads();

    #pragma unroll
    for (int u = 0; u < 4; u++) {
        int pos = atomicAdd(&sm->cur[bin_of(pv[u].x, pv[u].y)], 1);
        sm->srt[pos] = pv[u];
    }
    __syncthreads();

    // ---- query: warp-coherent 8x4 tiles ----
    int ilat = wrp * 8 + (lane & 7);
    int jlon = xb * 4 + (lane >> 3);
    float gx = __fmul_rn((float)ilat * (1.0f/128.0f), PI_F);
    float gy = __fmul_rn((float)(jlon - NLAT) * (1.0f/128.0f), PI_F);
    float g2 = gx*gx + gy*gy;
    float gx2 = 2.0f * gx, gy2 = 2.0f * gy;
    float domY = fmaxf(gy, 0.0f);
    float domY2 = domY * domY;

    int qbx = min(max((int)floorf((gx - X0) * (1.0f/HX)), 0), BINX-1);
    int qby = min(max((int)floorf((gy - Y0) * (1.0f/HY)), 0), BINY-1);

    float b0 = 3.4e38f, b1 = 3.4e38f, b2 = 3.4e38f;
    int   i0 = 0, i1 = 0, i2 = 0;

    #define SCAN_CELL(cx, cy) {                                             \
        int c = (cy) * BINX + (cx);                                         \
        int cnt = sm->cnt[c];                                               \
        if (cnt) {                                                          \
            float rx0 = X0 + (float)(cx) * HX;                              \
            float ry0 = Y0 + (float)(cy) * HY;                              \
            float ddx = fmaxf(fmaxf(rx0 - gx, gx - (rx0 + HX)), 0.0f);      \
            float ddy = fmaxf(fmaxf(ry0 - gy, gy - (ry0 + HY)), 0.0f);      \
            if (fmaf(ddx, ddx, ddy*ddy) < b2 + 1e-4f) {                     \
                int s = sm->start[c], e = s + cnt;                          \
                for (int t = s; t < e; t++) {                               \
                    float4 sp = sm->srt[t];                                 \
                    float cr = fmaf(gx2, sp.x, gy2 * sp.y);                 \
                    float d2 = (sp.z + g2) - cr;                            \
                    bool lt2 = d2 < b2, lt1 = d2 < b1, lt0 = d2 < b0;       \
                    i2 = lt1 ? i1 : (lt2 ? t : i2);                         \
                    b2 = lt1 ? b1 : (lt2 ? d2 : b2);                        \
                    i1 = lt0 ? i0 : (lt1 ? t : i1);                         \
                    b1 = lt0 ? b0 : (lt1 ? d2 : b1);                        \
                    i0 = lt0 ? t : i0;                                      \
                    b0 = lt0 ? d2 : b0;                                     \
                }                                                           \
            }                                                               \
        }                                                                   \
    }

    for (int r = 0; r < BINX + 2; r++) {
        int xl = qbx - r, xr = qbx + r, yl = qby - r, yr = qby + r;
        int cxl = max(xl, 0), cxr = min(xr, BINX-1);
        if (r == 0) {
            SCAN_CELL(qbx, qby);
        } else {
            if (yl >= 0)      for (int x2 = cxl; x2 <= cxr; x2++) SCAN_CELL(x2, yl);
            if (yr <= BINY-1) for (int x2 = cxl; x2 <= cxr; x2++) SCAN_CELL(x2, yr);
            int cyl = max(yl + 1, 0), cyr = min(yr - 1, BINY-1);
            if (xl >= 0)      for (int y2 = cyl; y2 <= cyr; y2++) SCAN_CELL(xl, y2);
            if (xr <= BINX-1) for (int y2 = cyl; y2 <= cyr; y2++) SCAN_CELL(xr, y2);
        }
        bool fullX = (xl <= 0) && (xr >= BINX-1);
        bool fullY = (yl <= 0) && (yr >= BINY-1);
        if (fullX && fullY) break;
        float dbx = 3.4e38f, dby = 3.4e38f;
        if (xl > 0)        dbx = fminf(dbx, gx - (X0 + (float)xl * HX));
        if (xr < BINX-1)   dbx = fminf(dbx, (X0 + (float)(xr+1) * HX) - gx);
        if (yl > 0)        dby = fminf(dby, gy - (Y0 + (float)yl * HY));
        if (yr < BINY-1)   dby = fminf(dby, fmaxf(0.0f, (Y0 + (float)(yr+1) * HY) - gy));
        float dlb2 = fminf(fmaf(dbx, dbx, domY2), dby * dby);
        if (b2 < dlb2 - 1e-4f) break;
    }
    #undef SCAN_CELL

    float4 p0 = sm->srt[i0], p1 = sm->srt[i1], p2 = sm->srt[i2];
    float dx, dy;
    dx = p0.x - gx; dy = p0.y - gy;
    float dd0 = sqrtf(__fadd_rn(__fmul_rn(dx,dx), __fmul_rn(dy,dy)));
    dx = p1.x - gx; dy = p1.y - gy;
    float dd1 = sqrtf(__fadd_rn(__fmul_rn(dx,dx), __fmul_rn(dy,dy)));
    dx = p2.x - gx; dy = p2.y - gy;
    float dd2 = sqrtf(__fadd_rn(__fmul_rn(dx,dx), __fmul_rn(dy,dy)));
    float sum = __fadd_rn(__fadd_rn(dd0, dd1), dd2);
    float w0 = __fdiv_rn(dd0, sum);
    float w1 = __fdiv_rn(dd1, sum);
    float w2 = __fdiv_rn(dd2, sum);
    float interp = __fadd_rn(__fadd_rn(__fmul_rn(p0.w, w0), __fmul_rn(p1.w, w1)),
                             __fmul_rn(p2.w, w2));

    g_ft[b][jlon][ilat] = interp;

    __syncthreads();
    __threadfence();
    if (tid == 0) atomicAdd(&g_arrive[b], 1);
}

// ---------------------------------------------------------------------------
// SHT role (identical to R10)
// ---------------------------------------------------------------------------
__device__ void sht_role(float* __restrict__ out, SmemSHT* sm,
                         int sbid, int tid) {
    int m = sbid % MMAX;
    int b = sbid / MMAX;
    int t = tid;

    if (t < NLON) sm->ctab[t] = cospif((float)t * (1.0f / 128.0f));
    if (t < 64) {
        int l = m + 1 + t;
        if (l < LMAX)
            sm->sa[t] = sqrtf((float)(4*l*l - 1) / (float)(l*l - m*m));
        int l2 = m + 2 + t;
        if (l2 < LMAX) {
            int lm = l2 - 1;
            sm->sbb[t] = sqrtf((float)(lm*lm - m*m) / (float)(4*lm*lm - 1));
        }
    }
    __syncthreads();

    if (t < 128) {
        int k = t;
        float tfrac = (float)k * (1.0f / 127.0f);
        float x = cospif(tfrac);
        float s = sinpif(tfrac);

        float c1 = cospif(2.0f * tfrac);
        float cprev = 1.0f, ccur = c1;
        float S = 0.0f;
        #pragma unroll 7
        for (int kk = 1; kk <= 63; kk++) {
            float coef = 2.0f * f_rcp((float)(4*kk*kk - 1));
            S = fmaf(coef, ccur, S);
            float cnext = fmaf(2.0f * c1, ccur, -cprev);
            cprev = ccur; ccur = cnext;
        }
        float w = (2.0f / 127.0f) * (1.0f - S);
        if (k == 0 || k == NLAT - 1) w *= 0.5f;

        float pr = 1.0f;
        for (int mm = 1; mm <= m; mm++)
            pr *= f_div((float)(2*mm + 1), (float)(2*mm));
        float pref = sqrtf(pr * (1.0f / (4.0f * PI_F)));

        float sgn = 1.0f, base = -s;
        int e = m;
        while (e) { if (e & 1) sgn *= base; base *= base; e >>= 1; }
        float pmm = pref * sgn;

        float* wrow = &sm->sW[k * LMAX];
        for (int l = 0; l < m; l++) wrow[l] = 0.0f;
        wrow[m] = pmm * w;
        if (m + 1 < LMAX) {
            float p2 = pmm;
            float p1 = sm->sa[0] * x * pmm;
            wrow[m+1] = p1 * w;
            for (int l = m + 2; l < LMAX; l++) {
                float p = sm->sa[l - m - 1] * (x * p1 - sm->sbb[l - m - 2] * p2);
                wrow[l] = p * w;
                p2 = p1; p1 = p;
            }
        }
    } else if (t == 511) {
        while (atomicAdd(&g_arrive[b], 0) < NN_BLOCKS / BATCH) __nanosleep(128);
        __threadfence();
    }
    __syncthreads();

    if (t >= 128 && t < 384) {
        int th = t - 128;
        int k = th & 127, half = th >> 7;
        const float* __restrict__ fp = &g_ft[b][half * 128][k];
        int base = (m * (half * 128)) & 255;
        float a0 = 0.f, a1 = 0.f;
        #pragma unroll 16
        for (int jj = 0; jj < 128; jj += 2) {
            float f0 = __ldg(&fp[(jj + 0) * NLAT]);
            float f1 = __ldg(&fp[(jj + 1) * NLAT]);
            int idx0 = (base + jj * m) & 255;
            int idx1 = (base + (jj + 1) * m) & 255;
            a0 = fmaf(f0, sm->ctab[idx0], a0);
            a1 = fmaf(f1, sm->ctab[idx1], a1);
        }
        sm->pf[half][k] = a0 + a1;
    }
    __syncthreads();
    if (t < NLAT)
        sm->fre[t] = (sm->pf[0][t] + sm->pf[1][t]) * (2.0f * PI_F / (float)NLON);
    __syncthreads();

    int g = t >> 6, l = t & 63;
    if (t < 256 && l < LMAX) {
        float p = 0.f;
        int k0 = g * 32;
        #pragma unroll 8
        for (int kk = k0; kk < k0 + 32; kk++)
            p = fmaf(sm->fre[kk], sm->sW[kk * LMAX + l], p);
        sm->ps[g][l] = p;
    }
    __syncthreads();
    if (t < LMAX)
        out[(b * LMAX + t) * MMAX + m] =
            (sm->ps[0][t] + sm->ps[1][t]) + (sm->ps[2][t] + sm->ps[3][t]);

    __syncthreads();
    if (t == 0) {
        __threadfence();
        int d = atomicAdd(&g_done, 1);
        if (d == SHT_BLOCKS - 1) {
            g_arrive[0] = 0;
            g_arrive[1] = 0;
            g_done = 0;
            __threadfence();
        }
    }
}

// ---------------------------------------------------------------------------
__global__ __launch_bounds__(512, 2) void k_all(const float* __restrict__ tgt,
                                                float* __restrict__ out) {
    __shared__ union { SmemNN nn; SmemSHT sht; } smem;
    int bid = blockIdx.x;
    int tid = threadIdx.x;
    if (bid < NN_BLOCKS) nn_role(tgt, &smem.nn, bid, tid);
    else                 sht_role(out, &smem.sht, bid - NN_BLOCKS, tid);
}

// ---------------------------------------------------------------------------
extern "C" void kernel_launch(void* const* d_in, const int* in_sizes, int n_in,
                              void* d_out, int out_size) {
    const float* tgt = (const float*)d_in[0];
    float* out = (float*)d_out;
    k_all<<<ALL_BLOCKS, 512>>>(tgt, out);
}

// round 15
// speedup vs baseline: 1.3080x; 1.3080x over previous
#include <cuda_runtime.h>
#include <math.h>

#define NLAT  128
#define NLON  256
#define LMAX  50
#define MMAX  50
#define BATCH 2
#define NPTS  2048
#define MGRID (NLAT*NLON)
#define PI_F  3.14159265358979323846f

#define BINX 32
#define BINY 16
#define NBIN (BINX*BINY)
#define HX (2.0f*PI_F/(float)BINX)
#define HY (PI_F/(float)BINY)
#define X0 (-PI_F)
#define Y0 (-PI_F)

#define NN_PER_B   32
#define NN_BLOCKS  (NN_PER_B*BATCH)   // 64
#define SHT_BLOCKS (MMAX*BATCH)       // 100
#define ALL_BLOCKS (NN_BLOCKS + SHT_BLOCKS)  // 164

__device__ float g_ft[BATCH][NLON][NLAT];   // interpolated grid, TRANSPOSED
__device__ int   g_arrive[BATCH] = {0, 0};
__device__ int   g_done = 0;

__device__ __forceinline__ float f_rcp(float v)  { float r; asm("rcp.approx.f32 %0,%1;"  : "=f"(r) : "f"(v)); return r; }
__device__ __forceinline__ float f_div(float a, float b){ float r; asm("div.approx.f32 %0,%1,%2;" : "=f"(r) : "f"(a), "f"(b)); return r; }

struct SmemNN {
    float4 srt[NPTS];            // 32 KB
    int cnt[NBIN];
    int start[NBIN];
    int cur[NBIN];
    int wsum[16];
};
struct SmemSHT {
    float ctab[NLON];
    float sW[NLAT * LMAX];       // 25.6 KB
    float sa[64];
    float sbb[64];
    float fre[NLAT];
    float pf[2][NLAT];
    float ps[4][64];
};

__device__ __forceinline__ int bin_of(float px, float py) {
    int bx = (int)floorf((px - X0) * (1.0f/HX));
    int by = (int)floorf((py - Y0) * (1.0f/HY));
    bx = min(max(bx, 0), BINX-1);
    by = min(max(by, 0), BINY-1);
    return by * BINX + bx;
}

// ---------------------------------------------------------------------------
// NN role: R10 build, then TWO warp-coherent 8x4 query tiles per warp.
// ---------------------------------------------------------------------------
__device__ void nn_role(const float* __restrict__ tgt, SmemNN* sm,
                        int nbid, int tid) {
    int b  = nbid / NN_PER_B;
    int xb = nbid % NN_PER_B;          // 0..31 -> 8 jlon columns each
    int lane = tid & 31, wrp = tid >> 5;

    float4 pv[4];
    #pragma unroll
    for (int u = 0; u < 4; u++) {
        int j = tid + u * 512;
        const float* tp = &tgt[(b * NPTS + j) * 3];
        float x = tp[0], y = tp[1], z = tp[2];
        float rho = sqrtf(x*x + y*y + z*z);
        float phi = atan2f(y, x);
        float th  = acosf(z / rho) - PI_F;
        float s2  = phi*phi + th*th;
        pv[u] = make_float4(phi, th, s2, rho);
    }

    if (tid < NBIN) sm->cnt[tid] = 0;
    __syncthreads();
    #pragma unroll
    for (int u = 0; u < 4; u++)
        atomicAdd(&sm->cnt[bin_of(pv[u].x, pv[u].y)], 1);
    __syncthreads();

    // warp-shfl scan over 512 bins
    int v = sm->cnt[tid];
    int x = v;
    #pragma unroll
    for (int off = 1; off < 32; off <<= 1) {
        int y = __shfl_up_sync(0xFFFFFFFFu, x, off);
        if (lane >= off) x += y;
    }
    if (lane == 31) sm->wsum[wrp] = x;
    __syncthreads();
    if (wrp == 0) {
        int w = (lane < 16) ? sm->wsum[lane] : 0;
        #pragma unroll
        for (int off = 1; off < 16; off <<= 1) {
            int y = __shfl_up_sync(0xFFFFFFFFu, w, off);
            if (lane >= off) w += y;
        }
        if (lane < 16) sm->wsum[lane] = w;
    }
    __syncthreads();
    int incl = x + (wrp > 0 ? sm->wsum[wrp - 1] : 0);
    sm->start[tid] = incl - v;
    sm->cur[tid]   = incl - v;
    __syncthreads();

    #pragma unroll
    for (int u = 0; u < 4; u++) {
        int pos = atomicAdd(&sm->cur[bin_of(pv[u].x, pv[u].y)], 1);
        sm->srt[pos] = pv[u];
    }
    __syncthreads();

    // ---- two query passes: warp covers ilat[8w,8w+8) x jlon[8xb,8xb+8) ----
    for (int pass = 0; pass < 2; pass++) {
        int ilat = wrp * 8 + (lane & 7);
        int jlon = xb * 8 + (lane >> 3) + pass * 4;
        float gx = __fmul_rn((float)ilat * (1.0f/128.0f), PI_F);
        float gy = __fmul_rn((float)(jlon - NLAT) * (1.0f/128.0f), PI_F);
        float g2 = gx*gx + gy*gy;
        float gx2 = 2.0f * gx, gy2 = 2.0f * gy;
        float domY = fmaxf(gy, 0.0f);
        float domY2 = domY * domY;

        int qbx = min(max((int)floorf((gx - X0) * (1.0f/HX)), 0), BINX-1);
        int qby = min(max((int)floorf((gy - Y0) * (1.0f/HY)), 0), BINY-1);

        float b0 = 3.4e38f, b1 = 3.4e38f, b2 = 3.4e38f;
        int   i0 = 0, i1 = 0, i2 = 0;

        #define SCAN_CELL(cx, cy) {                                             \
            int c = (cy) * BINX + (cx);                                         \
            int cnt = sm->cnt[c];                                               \
            if (cnt) {                                                          \
                float rx0 = X0 + (float)(cx) * HX;                              \
                float ry0 = Y0 + (float)(cy) * HY;                              \
                float ddx = fmaxf(fmaxf(rx0 - gx, gx - (rx0 + HX)), 0.0f);      \
                float ddy = fmaxf(fmaxf(ry0 - gy, gy - (ry0 + HY)), 0.0f);      \
                if (fmaf(ddx, ddx, ddy*ddy) < b2 + 1e-4f) {                     \
                    int s = sm->start[c], e = s + cnt;                          \
                    for (int t = s; t < e; t++) {                               \
                        float4 sp = sm->srt[t];                                 \
                        float cr = fmaf(gx2, sp.x, gy2 * sp.y);                 \
                        float d2 = (sp.z + g2) - cr;                            \
                        bool lt2 = d2 < b2, lt1 = d2 < b1, lt0 = d2 < b0;       \
                        i2 = lt1 ? i1 : (lt2 ? t : i2);                         \
                        b2 = lt1 ? b1 : (lt2 ? d2 : b2);                        \
                        i1 = lt0 ? i0 : (lt1 ? t : i1);                         \
                        b1 = lt0 ? b0 : (lt1 ? d2 : b1);                        \
                        i0 = lt0 ? t : i0;                                      \
                        b0 = lt0 ? d2 : b0;                                     \
                    }                                                           \
                }                                                               \
            }                                                                   \
        }

        for (int r = 0; r < BINX + 2; r++) {
            int xl = qbx - r, xr = qbx + r, yl = qby - r, yr = qby + r;
            int cxl = max(xl, 0), cxr = min(xr, BINX-1);
            if (r == 0) {
                SCAN_CELL(qbx, qby);
            } else {
                if (yl >= 0)      for (int x2 = cxl; x2 <= cxr; x2++) SCAN_CELL(x2, yl);
                if (yr <= BINY-1) for (int x2 = cxl; x2 <= cxr; x2++) SCAN_CELL(x2, yr);
                int cyl = max(yl + 1, 0), cyr = min(yr - 1, BINY-1);
                if (xl >= 0)      for (int y2 = cyl; y2 <= cyr; y2++) SCAN_CELL(xl, y2);
                if (xr <= BINX-1) for (int y2 = cyl; y2 <= cyr; y2++) SCAN_CELL(xr, y2);
            }
            bool fullX = (xl <= 0) && (xr >= BINX-1);
            bool fullY = (yl <= 0) && (yr >= BINY-1);
            if (fullX && fullY) break;
            float dbx = 3.4e38f, dby = 3.4e38f;
            if (xl > 0)        dbx = fminf(dbx, gx - (X0 + (float)xl * HX));
            if (xr < BINX-1)   dbx = fminf(dbx, (X0 + (float)(xr+1) * HX) - gx);
            if (yl > 0)        dby = fminf(dby, gy - (Y0 + (float)yl * HY));
            if (yr < BINY-1)   dby = fminf(dby, fmaxf(0.0f, (Y0 + (float)(yr+1) * HY) - gy));
            float dlb2 = fminf(fmaf(dbx, dbx, domY2), dby * dby);
            if (b2 < dlb2 - 1e-4f) break;
        }
        #undef SCAN_CELL

        float4 p0 = sm->srt[i0], p1 = sm->srt[i1], p2 = sm->srt[i2];
        float dx, dy;
        dx = p0.x - gx; dy = p0.y - gy;
        float dd0 = sqrtf(__fadd_rn(__fmul_rn(dx,dx), __fmul_rn(dy,dy)));
        dx = p1.x - gx; dy = p1.y - gy;
        float dd1 = sqrtf(__fadd_rn(__fmul_rn(dx,dx), __fmul_rn(dy,dy)));
        dx = p2.x - gx; dy = p2.y - gy;
        float dd2 = sqrtf(__fadd_rn(__fmul_rn(dx,dx), __fmul_rn(dy,dy)));
        float sum = __fadd_rn(__fadd_rn(dd0, dd1), dd2);
        float w0 = __fdiv_rn(dd0, sum);
        float w1 = __fdiv_rn(dd1, sum);
        float w2 = __fdiv_rn(dd2, sum);
        float interp = __fadd_rn(__fadd_rn(__fmul_rn(p0.w, w0), __fmul_rn(p1.w, w1)),
                                 __fmul_rn(p2.w, w2));

        g_ft[b][jlon][ilat] = interp;
    }

    __syncthreads();
    __threadfence();
    if (tid == 0) atomicAdd(&g_arrive[b], 1);
}

// ---------------------------------------------------------------------------
// SHT role (identical to R10; waits for 32 NN blocks per batch)
// ---------------------------------------------------------------------------
__device__ void sht_role(float* __restrict__ out, SmemSHT* sm,
                         int sbid, int tid) {
    int m = sbid % MMAX;
    int b = sbid / MMAX;
    int t = tid;

    if (t < NLON) sm->ctab[t] = cospif((float)t * (1.0f / 128.0f));
    if (t < 64) {
        int l = m + 1 + t;
        if (l < LMAX)
            sm->sa[t] = sqrtf((float)(4*l*l - 1) / (float)(l*l - m*m));
        int l2 = m + 2 + t;
        if (l2 < LMAX) {
            int lm = l2 - 1;
            sm->sbb[t] = sqrtf((float)(lm*lm - m*m) / (float)(4*lm*lm - 1));
        }
    }
    __syncthreads();

    if (t < 128) {
        int k = t;
        float tfrac = (float)k * (1.0f / 127.0f);
        float x = cospif(tfrac);
        float s = sinpif(tfrac);

        float c1 = cospif(2.0f * tfrac);
        float cprev = 1.0f, ccur = c1;
        float S = 0.0f;
        #pragma unroll 7
        for (int kk = 1; kk <= 63; kk++) {
            float coef = 2.0f * f_rcp((float)(4*kk*kk - 1));
            S = fmaf(coef, ccur, S);
            float cnext = fmaf(2.0f * c1, ccur, -cprev);
            cprev = ccur; ccur = cnext;
        }
        float w = (2.0f / 127.0f) * (1.0f - S);
        if (k == 0 || k == NLAT - 1) w *= 0.5f;

        float pr = 1.0f;
        for (int mm = 1; mm <= m; mm++)
            pr *= f_div((float)(2*mm + 1), (float)(2*mm));
        float pref = sqrtf(pr * (1.0f / (4.0f * PI_F)));

        float sgn = 1.0f, base = -s;
        int e = m;
        while (e) { if (e & 1) sgn *= base; base *= base; e >>= 1; }
        float pmm = pref * sgn;

        float* wrow = &sm->sW[k * LMAX];
        for (int l = 0; l < m; l++) wrow[l] = 0.0f;
        wrow[m] = pmm * w;
        if (m + 1 < LMAX) {
            float p2 = pmm;
            float p1 = sm->sa[0] * x * pmm;
            wrow[m+1] = p1 * w;
            for (int l = m + 2; l < LMAX; l++) {
                float p = sm->sa[l - m - 1] * (x * p1 - sm->sbb[l - m - 2] * p2);
                wrow[l] = p * w;
                p2 = p1; p1 = p;
            }
        }
    } else if (t == 511) {
        while (atomicAdd(&g_arrive[b], 0) < NN_PER_B) __nanosleep(128);
        __threadfence();
    }
    __syncthreads();

    if (t >= 128 && t < 384) {
        int th = t - 128;
        int k = th & 127, half = th >> 7;
        const float* __restrict__ fp = &g_ft[b][half * 128][k];
        int base = (m * (half * 128)) & 255;
        float a0 = 0.f, a1 = 0.f;
        #pragma unroll 16
        for (int jj = 0; jj < 128; jj += 2) {
            float f0 = __ldg(&fp[(jj + 0) * NLAT]);
            float f1 = __ldg(&fp[(jj + 1) * NLAT]);
            int idx0 = (base + jj * m) & 255;
            int idx1 = (base + (jj + 1) * m) & 255;
            a0 = fmaf(f0, sm->ctab[idx0], a0);
            a1 = fmaf(f1, sm->ctab[idx1], a1);
        }
        sm->pf[half][k] = a0 + a1;
    }
    __syncthreads();
    if (t < NLAT)
        sm->fre[t] = (sm->pf[0][t] + sm->pf[1][t]) * (2.0f * PI_F / (float)NLON);
    __syncthreads();

    int g = t >> 6, l = t & 63;
    if (t < 256 && l < LMAX) {
        float p = 0.f;
        int k0 = g * 32;
        #pragma unroll 8
        for (int kk = k0; kk < k0 + 32; kk++)
            p = fmaf(sm->fre[kk], sm->sW[kk * LMAX + l], p);
        sm->ps[g][l] = p;
    }
    __syncthreads();
    if (t < LMAX)
        out[(b * LMAX + t) * MMAX + m] =
            (sm->ps[0][t] + sm->ps[1][t]) + (sm->ps[2][t] + sm->ps[3][t]);

    __syncthreads();
    if (t == 0) {
        __threadfence();
        int d = atomicAdd(&g_done, 1);
        if (d == SHT_BLOCKS - 1) {
            g_arrive[0] = 0;
            g_arrive[1] = 0;
            g_done = 0;
            __threadfence();
        }
    }
}

// ---------------------------------------------------------------------------
__global__ __launch_bounds__(512, 2) void k_all(const float* __restrict__ tgt,
                                                float* __restrict__ out) {
    __shared__ union { SmemNN nn; SmemSHT sht; } smem;
    int bid = blockIdx.x;
    int tid = threadIdx.x;
    if (bid < NN_BLOCKS) nn_role(tgt, &smem.nn, bid, tid);
    else                 sht_role(out, &smem.sht, bid - NN_BLOCKS, tid);
}

// ---------------------------------------------------------------------------
extern "C" void kernel_launch(void* const* d_in, const int* in_sizes, int n_in,
                              void* d_out, int out_size) {
    const float* tgt = (const float*)d_in[0];
    float* out = (float*)d_out;
    k_all<<<ALL_BLOCKS, 512>>>(tgt, out);
}

// round 16
// speedup vs baseline: 1.8901x; 1.4451x over previous
#include <cuda_runtime.h>
#include <math.h>

#define NLAT  128
#define NLON  256
#define LMAX  50
#define MMAX  50
#define BATCH 2
#define NPTS  2048
#define MGRID (NLAT*NLON)
#define PI_F  3.14159265358979323846f

#define BINX 32
#define BINY 16
#define NBIN (BINX*BINY)
#define HX (2.0f*PI_F/(float)BINX)
#define HY (PI_F/(float)BINY)
#define X0 (-PI_F)
#define Y0 (-PI_F)

#define NN_BLOCKS  128           // 64 x BATCH
#define SHT_BLOCKS (MMAX*BATCH)  // 100
#define ALL_BLOCKS (NN_BLOCKS + SHT_BLOCKS)

__device__ float g_ft[BATCH][NLON][NLAT];   // interpolated grid, TRANSPOSED
__device__ int   g_arrive[BATCH] = {0, 0};
__device__ int   g_done = 0;

__device__ __forceinline__ float f_rcp(float v)  { float r; asm("rcp.approx.f32 %0,%1;"  : "=f"(r) : "f"(v)); return r; }
__device__ __forceinline__ float f_div(float a, float b){ float r; asm("div.approx.f32 %0,%1,%2;" : "=f"(r) : "f"(a), "f"(b)); return r; }

struct SmemNN {
    float4 srt[NPTS];            // 32 KB
    int cnt[NBIN];
    int start[NBIN];
    int cur[NBIN];
    int wsum[16];
};
struct SmemSHT {
    float ctab[NLON];
    float sW[NLAT * LMAX];       // 25.6 KB
    float sa[64];
    float sbb[64];
    float fre[NLAT];
    float pf[2][NLAT];
    float ps[4][64];
};

__device__ __forceinline__ int bin_of(float px, float py) {
    int bx = (int)floorf((px - X0) * (1.0f/HX));
    int by = (int)floorf((py - Y0) * (1.0f/HY));
    bx = min(max(bx, 0), BINX-1);
    by = min(max(by, 0), BINY-1);
    return by * BINX + bx;
}

// ---------------------------------------------------------------------------
// NN role (exact R10 structure + branchless top-3 insert)
// ---------------------------------------------------------------------------
__device__ void nn_role(const float* __restrict__ tgt, SmemNN* sm,
                        int nbid, int tid) {
    int b = nbid >> 6;
    int xb = nbid & 63;
    int lane = tid & 31, wrp = tid >> 5;

    float4 pv[4];
    #pragma unroll
    for (int u = 0; u < 4; u++) {
        int j = tid + u * 512;
        const float* tp = &tgt[(b * NPTS + j) * 3];
        float x = tp[0], y = tp[1], z = tp[2];
        float rho = sqrtf(x*x + y*y + z*z);
        float phi = atan2f(y, x);
        float th  = acosf(z / rho) - PI_F;
        float s2  = phi*phi + th*th;
        pv[u] = make_float4(phi, th, s2, rho);
    }

    if (tid < NBIN) sm->cnt[tid] = 0;
    __syncthreads();
    #pragma unroll
    for (int u = 0; u < 4; u++)
        atomicAdd(&sm->cnt[bin_of(pv[u].x, pv[u].y)], 1);
    __syncthreads();

    // warp-shfl scan over 512 bins
    int v = sm->cnt[tid];
    int x = v;
    #pragma unroll
    for (int off = 1; off < 32; off <<= 1) {
        int y = __shfl_up_sync(0xFFFFFFFFu, x, off);
        if (lane >= off) x += y;
    }
    if (lane == 31) sm->wsum[wrp] = x;
    __syncthreads();
    if (wrp == 0) {
        int w = (lane < 16) ? sm->wsum[lane] : 0;
        #pragma unroll
        for (int off = 1; off < 16; off <<= 1) {
            int y = __shfl_up_sync(0xFFFFFFFFu, w, off);
            if (lane >= off) w += y;
        }
        if (lane < 16) sm->wsum[lane] = w;
    }
    __syncthreads();
    int incl = x + (wrp > 0 ? sm->wsum[wrp - 1] : 0);
    sm->start[tid] = incl - v;
    sm->cur[tid]   = incl - v;
    __syncthreads();

    #pragma unroll
    for (int u = 0; u < 4; u++) {
        int pos = atomicAdd(&sm->cur[bin_of(pv[u].x, pv[u].y)], 1);
        sm->srt[pos] = pv[u];
    }
    __syncthreads();

    // ---- query: warp-coherent 8x4 tiles ----
    int ilat = wrp * 8 + (lane & 7);
    int jlon = xb * 4 + (lane >> 3);
    float gx = __fmul_rn((float)ilat * (1.0f/128.0f), PI_F);
    float gy = __fmul_rn((float)(jlon - NLAT) * (1.0f/128.0f), PI_F);
    float g2 = gx*gx + gy*gy;
    float gx2 = 2.0f * gx, gy2 = 2.0f * gy;
    float domY = fmaxf(gy, 0.0f);
    float domY2 = domY * domY;

    int qbx = min(max((int)floorf((gx - X0) * (1.0f/HX)), 0), BINX-1);
    int qby = min(max((int)floorf((gy - Y0) * (1.0f/HY)), 0), BINY-1);

    float b0 = 3.4e38f, b1 = 3.4e38f, b2 = 3.4e38f;
    int   i0 = 0, i1 = 0, i2 = 0;

    // branchless top-3 insert (comparisons identical to branchy version)
    #define SCAN_CELL(cx, cy) {                                             \
        int c = (cy) * BINX + (cx);                                         \
        int cnt = sm->cnt[c];                                               \
        if (cnt) {                                                          \
            float rx0 = X0 + (float)(cx) * HX;                              \
            float ry0 = Y0 + (float)(cy) * HY;                              \
            float ddx = fmaxf(fmaxf(rx0 - gx, gx - (rx0 + HX)), 0.0f);      \
            float ddy = fmaxf(fmaxf(ry0 - gy, gy - (ry0 + HY)), 0.0f);      \
            if (fmaf(ddx, ddx, ddy*ddy) < b2 + 1e-4f) {                     \
                int s = sm->start[c], e = s + cnt;                          \
                for (int t = s; t < e; t++) {                               \
                    float4 sp = sm->srt[t];                                 \
                    float cr = fmaf(gx2, sp.x, gy2 * sp.y);                 \
                    float d2 = (sp.z + g2) - cr;                            \
                    bool lt2 = d2 < b2, lt1 = d2 < b1, lt0 = d2 < b0;       \
                    i2 = lt1 ? i1 : (lt2 ? t : i2);                         \
                    b2 = lt1 ? b1 : (lt2 ? d2 : b2);                        \
                    i1 = lt0 ? i0 : (lt1 ? t : i1);                         \
                    b1 = lt0 ? b0 : (lt1 ? d2 : b1);                        \
                    i0 = lt0 ? t : i0;                                      \
                    b0 = lt0 ? d2 : b0;                                     \
                }                                                           \
            }                                                               \
        }                                                                   \
    }

    for (int r = 0; r < BINX + 2; r++) {
        int xl = qbx - r, xr = qbx + r, yl = qby - r, yr = qby + r;
        int cxl = max(xl, 0), cxr = min(xr, BINX-1);
        if (r == 0) {
            SCAN_CELL(qbx, qby);
        } else {
            if (yl >= 0)      for (int x2 = cxl; x2 <= cxr; x2++) SCAN_CELL(x2, yl);
            if (yr <= BINY-1) for (int x2 = cxl; x2 <= cxr; x2++) SCAN_CELL(x2, yr);
            int cyl = max(yl + 1, 0), cyr = min(yr - 1, BINY-1);
            if (xl >= 0)      for (int y2 = cyl; y2 <= cyr; y2++) SCAN_CELL(xl, y2);
            if (xr <= BINX-1) for (int y2 = cyl; y2 <= cyr; y2++) SCAN_CELL(xr, y2);
        }
        bool fullX = (xl <= 0) && (xr >= BINX-1);
        bool fullY = (yl <= 0) && (yr >= BINY-1);
        if (fullX && fullY) break;
        float dbx = 3.4e38f, dby = 3.4e38f;
        if (xl > 0)        dbx = fminf(dbx, gx - (X0 + (float)xl * HX));
        if (xr < BINX-1)   dbx = fminf(dbx, (X0 + (float)(xr+1) * HX) - gx);
        if (yl > 0)        dby = fminf(dby, gy - (Y0 + (float)yl * HY));
        if (yr < BINY-1)   dby = fminf(dby, fmaxf(0.0f, (Y0 + (float)(yr+1) * HY) - gy));
        float dlb2 = fminf(fmaf(dbx, dbx, domY2), dby * dby);
        if (b2 < dlb2 - 1e-4f) break;
    }
    #undef SCAN_CELL

    float4 p0 = sm->srt[i0], p1 = sm->srt[i1], p2 = sm->srt[i2];
    float dx, dy;
    dx = p0.x - gx; dy = p0.y - gy;
    float dd0 = sqrtf(__fadd_rn(__fmul_rn(dx,dx), __fmul_rn(dy,dy)));
    dx = p1.x - gx; dy = p1.y - gy;
    float dd1 = sqrtf(__fadd_rn(__fmul_rn(dx,dx), __fmul_rn(dy,dy)));
    dx = p2.x - gx; dy = p2.y - gy;
    float dd2 = sqrtf(__fadd_rn(__fmul_rn(dx,dx), __fmul_rn(dy,dy)));
    float sum = __fadd_rn(__fadd_rn(dd0, dd1), dd2);
    float w0 = __fdiv_rn(dd0, sum);
    float w1 = __fdiv_rn(dd1, sum);
    float w2 = __fdiv_rn(dd2, sum);
    float interp = __fadd_rn(__fadd_rn(__fmul_rn(p0.w, w0), __fmul_rn(p1.w, w1)),
                             __fmul_rn(p2.w, w2));

    g_ft[b][jlon][ilat] = interp;

    __syncthreads();
    __threadfence();
    if (tid == 0) atomicAdd(&g_arrive[b], 1);
}

// ---------------------------------------------------------------------------
// SHT role (identical to R10)
// ---------------------------------------------------------------------------
__device__ void sht_role(float* __restrict__ out, SmemSHT* sm,
                         int sbid, int tid) {
    int m = sbid % MMAX;
    int b = sbid / MMAX;
    int t = tid;

    if (t < NLON) sm->ctab[t] = cospif((float)t * (1.0f / 128.0f));
    if (t < 64) {
        int l = m + 1 + t;
        if (l < LMAX)
            sm->sa[t] = sqrtf((float)(4*l*l - 1) / (float)(l*l - m*m));
        int l2 = m + 2 + t;
        if (l2 < LMAX) {
            int lm = l2 - 1;
            sm->sbb[t] = sqrtf((float)(lm*lm - m*m) / (float)(4*lm*lm - 1));
        }
    }
    __syncthreads();

    if (t < 128) {
        int k = t;
        float tfrac = (float)k * (1.0f / 127.0f);
        float x = cospif(tfrac);
        float s = sinpif(tfrac);

        float c1 = cospif(2.0f * tfrac);
        float cprev = 1.0f, ccur = c1;
        float S = 0.0f;
        #pragma unroll 7
        for (int kk = 1; kk <= 63; kk++) {
            float coef = 2.0f * f_rcp((float)(4*kk*kk - 1));
            S = fmaf(coef, ccur, S);
            float cnext = fmaf(2.0f * c1, ccur, -cprev);
            cprev = ccur; ccur = cnext;
        }
        float w = (2.0f / 127.0f) * (1.0f - S);
        if (k == 0 || k == NLAT - 1) w *= 0.5f;

        float pr = 1.0f;
        for (int mm = 1; mm <= m; mm++)
            pr *= f_div((float)(2*mm + 1), (float)(2*mm));
        float pref = sqrtf(pr * (1.0f / (4.0f * PI_F)));

        float sgn = 1.0f, base = -s;
        int e = m;
        while (e) { if (e & 1) sgn *= base; base *= base; e >>= 1; }
        float pmm = pref * sgn;

        float* wrow = &sm->sW[k * LMAX];
        for (int l = 0; l < m; l++) wrow[l] = 0.0f;
        wrow[m] = pmm * w;
        if (m + 1 < LMAX) {
            float p2 = pmm;
            float p1 = sm->sa[0] * x * pmm;
            wrow[m+1] = p1 * w;
            for (int l = m + 2; l < LMAX; l++) {
                float p = sm->sa[l - m - 1] * (x * p1 - sm->sbb[l - m - 2] * p2);
                wrow[l] = p * w;
                p2 = p1; p1 = p;
            }
        }
    } else if (t == 511) {
        while (atomicAdd(&g_arrive[b], 0) < NN_BLOCKS / BATCH) __nanosleep(128);
        __threadfence();
    }
    __syncthreads();

    if (t >= 128 && t < 384) {
        int th = t - 128;
        int k = th & 127, half = th >> 7;
        const float* __restrict__ fp = &g_ft[b][half * 128][k];
        int base = (m * (half * 128)) & 255;
        float a0 = 0.f, a1 = 0.f;
        #pragma unroll 16
        for (int jj = 0; jj < 128; jj += 2) {
            float f0 = __ldg(&fp[(jj + 0) * NLAT]);
            float f1 = __ldg(&fp[(jj + 1) * NLAT]);
            int idx0 = (base + jj * m) & 255;
            int idx1 = (base + (jj + 1) * m) & 255;
            a0 = fmaf(f0, sm->ctab[idx0], a0);
            a1 = fmaf(f1, sm->ctab[idx1], a1);
        }
        sm->pf[half][k] = a0 + a1;
    }
    __syncthreads();
    if (t < NLAT)
        sm->fre[t] = (sm->pf[0][t] + sm->pf[1][t]) * (2.0f * PI_F / (float)NLON);
    __syncthreads();

    int g = t >> 6, l = t & 63;
    if (t < 256 && l < LMAX) {
        float p = 0.f;
        int k0 = g * 32;
        #pragma unroll 8
        for (int kk = k0; kk < k0 + 32; kk++)
            p = fmaf(sm->fre[kk], sm->sW[kk * LMAX + l], p);
        sm->ps[g][l] = p;
    }
    __syncthreads();
    if (t < LMAX)
        out[(b * LMAX + t) * MMAX + m] =
            (sm->ps[0][t] + sm->ps[1][t]) + (sm->ps[2][t] + sm->ps[3][t]);

    __syncthreads();
    if (t == 0) {
        __threadfence();
        int d = atomicAdd(&g_done, 1);
        if (d == SHT_BLOCKS - 1) {
            g_arrive[0] = 0;
            g_arrive[1] = 0;
            g_done = 0;
            __threadfence();
        }
    }
}

// ---------------------------------------------------------------------------
__global__ __launch_bounds__(512, 2) void k_all(const float* __restrict__ tgt,
                                                float* __restrict__ out) {
    __shared__ union { SmemNN nn; SmemSHT sht; } smem;
    int bid = blockIdx.x;
    int tid = threadIdx.x;
    if (bid < NN_BLOCKS) nn_role(tgt, &smem.nn, bid, tid);
    else                 sht_role(out, &smem.sht, bid - NN_BLOCKS, tid);
}

// ---------------------------------------------------------------------------
extern "C" void kernel_launch(void* const* d_in, const int* in_sizes, int n_in,
                              void* d_out, int out_size) {
    const float* tgt = (const float*)d_in[0];
    float* out = (float*)d_out;
    k_all<<<ALL_BLOCKS, 512>>>(tgt, out);
}